// round 1
// baseline (speedup 1.0000x reference)
#include <cuda_runtime.h>
#include <cstdint>

#define B_ROWS 32768
#define FDIM   512
#define GRP    16
#define LBL    64
#define NCLS   1000
#define NCOLS  1024      // GRP*LBL
#define TM     32        // rows per CTA
#define BK     16        // k tile
#define WPITCH 1025      // padded w_sm row (conflict-free stores)
#define THREADS 256

// smem layout (float indices):
//  [0,512)       gp_sm   [TM][GRP]
//  [512,1536)    bias_sm [NCOLS]
//  [1536,2537)   off_sm  (int)[NCLS+1]
//  [2560,3584)   src_sm  (int)[NCOLS]
//  [3584, ...)   UNION:
//     GEMM phase: a_sm [BK][TM] (512 f) then w_sm [BK][WPITCH] (16400 f)
//     EPI  phase: wsm  [TM][NCOLS] (32768 f)
#define SMEM_FLOATS (3584 + TM * NCOLS)
#define SMEM_BYTES  (SMEM_FLOATS * 4)

__device__ int g_cls_off[NCLS + 1];
__device__ int g_cls_src[NCOLS];

// Deterministic inversion of label_ids: per class c, ordered list of source
// columns (g*64+l). No atomics -> bitwise-stable ordering across runs.
__global__ void prep_kernel(const int* __restrict__ label_ids) {
    __shared__ int lab[NCOLS];
    __shared__ int cnt[NCLS];
    __shared__ int off[NCLS + 1];
    int t = threadIdx.x;
    lab[t] = label_ids[t];
    __syncthreads();
    if (t < NCLS) {
        int c = 0;
        for (int i = 0; i < NCOLS; i++) c += (lab[i] == t);
        cnt[t] = c;
    }
    __syncthreads();
    if (t == 0) {
        int acc = 0;
        for (int c = 0; c < NCLS; c++) { off[c] = acc; acc += cnt[c]; }
        off[NCLS] = acc;
    }
    __syncthreads();
    if (t <= NCLS) g_cls_off[t] = off[t];
    if (t < NCLS) {
        int pos = off[t];
        for (int i = 0; i < NCOLS; i++)
            if (lab[i] == t) g_cls_src[pos++] = i;
    }
}

extern __shared__ float smem[];

__global__ void __launch_bounds__(THREADS, 1)
mhc_kernel(const float* __restrict__ features,
           const float* __restrict__ gprob,
           const float* __restrict__ W,
           const float* __restrict__ bias,
           float* __restrict__ out) {
    float* gp_sm   = smem;
    float* bias_sm = smem + 512;
    int*   off_sm  = (int*)(smem + 1536);
    int*   src_sm  = (int*)(smem + 2560);
    float* uni     = smem + 3584;          // 16B aligned (3584*4 = 14336)
    float* a_sm    = uni;                  // [BK][TM]
    float* w_sm    = uni + 512;            // [BK][WPITCH]
    float* wsm     = uni;                  // [TM][NCOLS] (epilogue, aliases tiles)

    const int t    = threadIdx.x;
    const int row0 = blockIdx.x * TM;
    const int tx   = t & 63;   // col thread: cols n = j*64 + tx, j = 0..15 (j == group id)
    const int ty   = t >> 6;   // row thread: rows ty*8 .. ty*8+7

    // small tables (consumed only after the k-loop's syncs)
    for (int i = t; i < TM * GRP; i += THREADS) gp_sm[i] = gprob[row0 * GRP + i];
    for (int i = t; i < NCOLS; i += THREADS)    bias_sm[i] = bias[i];
    for (int i = t; i < NCLS + 1; i += THREADS) off_sm[i] = g_cls_off[i];
    for (int i = t; i < NCOLS; i += THREADS)    src_sm[i] = g_cls_src[i];

    // packed accumulators: acc[r2][j] holds rows (ty*8+2*r2, ty*8+2*r2+1), col j*64+tx
    unsigned long long acc[4][16];
#pragma unroll
    for (int r2 = 0; r2 < 4; r2++)
#pragma unroll
        for (int j = 0; j < 16; j++) acc[r2][j] = 0ull;

    for (int kt = 0; kt < FDIM; kt += BK) {
        __syncthreads();
        // --- A tile: 32 rows x 16 k, float4 per thread (threads 0..127) ---
        if (t < 128) {
            int r  = t >> 2;
            int kq = (t & 3) * 4;
            const float4 v = *(const float4*)(features + (size_t)(row0 + r) * FDIM + kt + kq);
            a_sm[(kq + 0) * TM + r] = v.x;
            a_sm[(kq + 1) * TM + r] = v.y;
            a_sm[(kq + 2) * TM + r] = v.z;
            a_sm[(kq + 3) * TM + r] = v.w;
        }
        // --- W tile: 1024 n x 16 k, 16 float4 per thread ---
#pragma unroll
        for (int i = 0; i < 16; i++) {
            int idx = i * THREADS + t;
            int n   = idx >> 2;
            int kq  = (idx & 3) * 4;
            const float4 v = *(const float4*)(W + (size_t)n * FDIM + kt + kq);
            w_sm[(kq + 0) * WPITCH + n] = v.x;
            w_sm[(kq + 1) * WPITCH + n] = v.y;
            w_sm[(kq + 2) * WPITCH + n] = v.z;
            w_sm[(kq + 3) * WPITCH + n] = v.w;
        }
        __syncthreads();

#pragma unroll
        for (int k = 0; k < BK; k++) {
            const unsigned long long* ap =
                (const unsigned long long*)(a_sm + k * TM + ty * 8);
            unsigned long long a0 = ap[0], a1 = ap[1], a2v = ap[2], a3 = ap[3];
#pragma unroll
            for (int j = 0; j < 16; j++) {
                unsigned int wb = __float_as_uint(w_sm[k * WPITCH + j * 64 + tx]);
                unsigned long long w2;
                asm("mov.b64 %0, {%1, %1};" : "=l"(w2) : "r"(wb));
                asm("fma.rn.f32x2 %0, %1, %2, %0;" : "+l"(acc[0][j]) : "l"(a0),  "l"(w2));
                asm("fma.rn.f32x2 %0, %1, %2, %0;" : "+l"(acc[1][j]) : "l"(a1),  "l"(w2));
                asm("fma.rn.f32x2 %0, %1, %2, %0;" : "+l"(acc[2][j]) : "l"(a2v), "l"(w2));
                asm("fma.rn.f32x2 %0, %1, %2, %0;" : "+l"(acc[3][j]) : "l"(a3),  "l"(w2));
            }
        }
    }

    __syncthreads();  // k-loop tiles dead; union becomes weighted buffer

    // --- epilogue: bias + group-prob weighting into wsm ---
#pragma unroll
    for (int r2 = 0; r2 < 4; r2++) {
        int rlo = ty * 8 + 2 * r2;
#pragma unroll
        for (int j = 0; j < 16; j++) {
            int n = j * 64 + tx;               // group id == j
            float vlo = __uint_as_float((unsigned)(acc[r2][j] & 0xffffffffu));
            float vhi = __uint_as_float((unsigned)(acc[r2][j] >> 32));
            float bn  = bias_sm[n];
            wsm[rlo * NCOLS + n]       = gp_sm[rlo * GRP + j]       * (vlo + bn);
            wsm[(rlo + 1) * NCOLS + n] = gp_sm[(rlo + 1) * GRP + j] * (vhi + bn);
        }
    }
    __syncthreads();

    // --- scatter: out[b, c] = sum over sources of class c (coalesced stores) ---
    for (int c = t; c < NCLS; c += THREADS) {
        int s0 = off_sm[c], s1 = off_sm[c + 1];
#pragma unroll 4
        for (int r = 0; r < TM; r++) {
            float s = 0.f;
            for (int k = s0; k < s1; k++) s += wsm[r * NCOLS + src_sm[k]];
            out[(size_t)(row0 + r) * NCLS + c] = s;
        }
    }
}

extern "C" void kernel_launch(void* const* d_in, const int* in_sizes, int n_in,
                              void* d_out, int out_size) {
    const float* features = (const float*)d_in[0];
    const float* gprob    = (const float*)d_in[1];
    const float* W        = (const float*)d_in[2];
    const float* bias     = (const float*)d_in[3];
    const int*   labels   = (const int*)d_in[4];
    float* out = (float*)d_out;

    cudaFuncSetAttribute(mhc_kernel, cudaFuncAttributeMaxDynamicSharedMemorySize,
                         SMEM_BYTES);

    prep_kernel<<<1, 1024>>>(labels);
    mhc_kernel<<<B_ROWS / TM, THREADS, SMEM_BYTES>>>(features, gprob, W, bias, out);
}

// round 3
// speedup vs baseline: 1.5758x; 1.5758x over previous
#include <cuda_runtime.h>
#include <cuda_bf16.h>
#include <mma.h>
#include <cstdint>

using namespace nvcuda;

#define B_ROWS 32768
#define FDIM   512
#define NCOLS  1024
#define NCLS   1000

#define BM 128
#define BN 128
#define BK 32
#define LDA 40        // bf16 smem pitch (80B: 16B-aligned, ldmatrix conflict-free)
#define LDE 136       // fp32 epilogue pitch (544B, 16B-aligned)
#define NIT 48        // 3 passes * (512/32)
#define STAGE_BYTES 20480   // A(128*40*2=10240) + W(10240)
#define SMEM_GEMM   (BM * LDE * 4)   // 69632 (>= 2*STAGE_BYTES)

#define SMEM_SCAT (32*1024*4 + 4096 + 4096)

// ---- device globals (legal scratch) ----
__device__ int   g_cls_off[NCLS + 1];
__device__ int   g_cls_src[NCOLS];
__device__ __nv_bfloat16 g_Ahi[(size_t)B_ROWS * FDIM];
__device__ __nv_bfloat16 g_Alo[(size_t)B_ROWS * FDIM];
__device__ __nv_bfloat16 g_Whi[NCOLS * FDIM];
__device__ __nv_bfloat16 g_Wlo[NCOLS * FDIM];
__device__ float g_scratch[(size_t)B_ROWS * NCOLS];

__device__ __forceinline__ uint32_t smem_u32(const void* p) {
    uint32_t a;
    asm("{ .reg .u64 t; cvta.to.shared.u64 t, %1; cvt.u32.u64 %0, t; }" : "=r"(a) : "l"(p));
    return a;
}
__device__ __forceinline__ void cp16(uint32_t dst, const void* src) {
    asm volatile("cp.async.cg.shared.global [%0], [%1], 16;" :: "r"(dst), "l"(src) : "memory");
}

// ---- prep: deterministic CSR of label_ids ----
__global__ void prep_kernel(const int* __restrict__ label_ids) {
    __shared__ int lab[NCOLS];
    __shared__ int cnt[NCLS];
    __shared__ int off[NCLS + 1];
    int t = threadIdx.x;
    lab[t] = label_ids[t];
    __syncthreads();
    if (t < NCLS) {
        int c = 0;
        for (int i = 0; i < NCOLS; i++) c += (lab[i] == t);
        cnt[t] = c;
    }
    __syncthreads();
    if (t == 0) {
        int acc = 0;
        for (int c = 0; c < NCLS; c++) { off[c] = acc; acc += cnt[c]; }
        off[NCLS] = acc;
    }
    __syncthreads();
    if (t <= NCLS) g_cls_off[t] = off[t];
    if (t < NCLS) {
        int pos = off[t];
        for (int i = 0; i < NCOLS; i++)
            if (lab[i] == t) g_cls_src[pos++] = i;
    }
}

// ---- prep: fp32 -> bf16 hi/lo (4 elems/thread) ----
__global__ void prep_split(const float* __restrict__ src,
                           __nv_bfloat16* __restrict__ hi,
                           __nv_bfloat16* __restrict__ lo) {
    size_t i0 = ((size_t)blockIdx.x * 256 + threadIdx.x) * 4;
    float4 v = *(const float4*)(src + i0);
    __nv_bfloat16 h[4], l[4];
    float x;
    x = v.x; h[0] = __float2bfloat16_rn(x); l[0] = __float2bfloat16_rn(x - __bfloat162float(h[0]));
    x = v.y; h[1] = __float2bfloat16_rn(x); l[1] = __float2bfloat16_rn(x - __bfloat162float(h[1]));
    x = v.z; h[2] = __float2bfloat16_rn(x); l[2] = __float2bfloat16_rn(x - __bfloat162float(h[2]));
    x = v.w; h[3] = __float2bfloat16_rn(x); l[3] = __float2bfloat16_rn(x - __bfloat162float(h[3]));
    *(uint2*)(hi + i0) = *(uint2*)h;
    *(uint2*)(lo + i0) = *(uint2*)l;
}

// ---- GEMM: bf16 WMMA, 3-product split, cp.async double buffer ----
__global__ void __launch_bounds__(256)
mhc_gemm(const float* __restrict__ gprob, const float* __restrict__ bias) {
    extern __shared__ char smem[];
    const uint32_t sb = smem_u32(smem);
    const int t   = threadIdx.x;
    const int wid = t >> 5;
    const int n0   = blockIdx.x * BN;
    const int row0 = blockIdx.y * BM;
    const int wm0 = (wid & 3) * 32;   // warp tile rows
    const int wn0 = (wid >> 2) * 64;  // warp tile cols

    wmma::fragment<wmma::accumulator, 16, 16, 16, float> acc[2][4];
#pragma unroll
    for (int fm = 0; fm < 2; fm++)
#pragma unroll
        for (int fn = 0; fn < 4; fn++) wmma::fill_fragment(acc[fm][fn], 0.0f);

    // per-thread cp.async indices: 512 16B-chunks per operand tile, 2 each
    const int r0c = t >> 2, c0c = (t & 3) * 16;         // chunk set 0: rows 0..63
    const int r1c = 64 + r0c;                           // chunk set 1: rows 64..127

    auto issue = [&](int it, int s) {
        if (it < NIT) {
            int p = it >> 4, kc = it & 15;
            const __nv_bfloat16* As = (p == 2) ? g_Alo : g_Ahi;
            const __nv_bfloat16* Ws = (p == 1) ? g_Wlo : g_Whi;
            const char* asrc = (const char*)(As + (size_t)row0 * FDIM + kc * BK);
            const char* wsrc = (const char*)(Ws + (size_t)n0 * FDIM + kc * BK);
            uint32_t adst = sb + s * STAGE_BYTES;
            uint32_t wdst = adst + 10240;
            cp16(adst + r0c * 80 + c0c, asrc + (size_t)r0c * 1024 + c0c);
            cp16(adst + r1c * 80 + c0c, asrc + (size_t)r1c * 1024 + c0c);
            cp16(wdst + r0c * 80 + c0c, wsrc + (size_t)r0c * 1024 + c0c);
            cp16(wdst + r1c * 80 + c0c, wsrc + (size_t)r1c * 1024 + c0c);
        }
        asm volatile("cp.async.commit_group;" ::: "memory");
    };

    issue(0, 0);
    for (int it = 0; it < NIT; ++it) {
        int s = it & 1;
        issue(it + 1, s ^ 1);
        asm volatile("cp.async.wait_group 1;" ::: "memory");
        __syncthreads();

        const __nv_bfloat16* a_sm = (const __nv_bfloat16*)(smem + s * STAGE_BYTES);
        const __nv_bfloat16* w_sm = (const __nv_bfloat16*)(smem + s * STAGE_BYTES + 10240);
#pragma unroll
        for (int kk = 0; kk < BK; kk += 16) {
            wmma::fragment<wmma::matrix_a, 16, 16, 16, __nv_bfloat16, wmma::row_major> af[2];
            wmma::fragment<wmma::matrix_b, 16, 16, 16, __nv_bfloat16, wmma::col_major> bfr[4];
#pragma unroll
            for (int fm = 0; fm < 2; fm++)
                wmma::load_matrix_sync(af[fm], a_sm + (wm0 + fm * 16) * LDA + kk, LDA);
#pragma unroll
            for (int fn = 0; fn < 4; fn++)
                wmma::load_matrix_sync(bfr[fn], w_sm + (wn0 + fn * 16) * LDA + kk, LDA);
#pragma unroll
            for (int fm = 0; fm < 2; fm++)
#pragma unroll
                for (int fn = 0; fn < 4; fn++)
                    wmma::mma_sync(acc[fm][fn], af[fm], bfr[fn], acc[fm][fn]);
        }
        __syncthreads();   // all warps done with stage s before it+2 overwrites it
    }

    // ---- epilogue: frags -> smem -> (bias+gprob) -> scratch ----
    float* epi = (float*)smem;
#pragma unroll
    for (int fm = 0; fm < 2; fm++)
#pragma unroll
        for (int fn = 0; fn < 4; fn++)
            wmma::store_matrix_sync(epi + (wm0 + fm * 16) * LDE + wn0 + fn * 16,
                                    acc[fm][fn], LDE, wmma::mem_row_major);
    __syncthreads();

#pragma unroll
    for (int i = 0; i < 16; i++) {
        int idx = i * 256 + t;          // 4096 float4s in the 128x128 tile
        int r  = idx >> 5;
        int c4 = (idx & 31) * 4;
        float4 v = *(float4*)(epi + r * LDE + c4);
        int n = n0 + c4;
        float gp = __ldg(gprob + (size_t)(row0 + r) * 16 + (n >> 6));
        v.x = (v.x + __ldg(bias + n + 0)) * gp;
        v.y = (v.y + __ldg(bias + n + 1)) * gp;
        v.z = (v.z + __ldg(bias + n + 2)) * gp;
        v.w = (v.w + __ldg(bias + n + 3)) * gp;
        *(float4*)(g_scratch + (size_t)(row0 + r) * NCOLS + n) = v;
    }
}

// ---- scatter: CSR gather scratch -> out ----
__global__ void __launch_bounds__(256, 1)
mhc_scatter(float* __restrict__ out) {
    extern __shared__ char smem[];
    float* wsm    = (float*)smem;                 // [32][1024]
    int*   off_sm = (int*)(smem + 131072);
    int*   src_sm = (int*)(smem + 135168);
    const int t = threadIdx.x;
    const int r0 = blockIdx.x * 32;

    for (int i = t; i <= NCLS; i += 256) off_sm[i] = g_cls_off[i];
    for (int i = t; i < NCOLS; i += 256) src_sm[i] = g_cls_src[i];

    const float4* src = (const float4*)(g_scratch + (size_t)r0 * NCOLS);
    float4* dst4 = (float4*)wsm;
    for (int i = t; i < 32 * NCOLS / 4; i += 256) dst4[i] = src[i];
    __syncthreads();

    for (int c = t; c < NCLS; c += 256) {
        int s0 = off_sm[c], s1 = off_sm[c + 1];
#pragma unroll 4
        for (int r = 0; r < 32; r++) {
            float s = 0.f;
            for (int k = s0; k < s1; k++) s += wsm[r * NCOLS + src_sm[k]];
            out[(size_t)(r0 + r) * NCLS + c] = s;
        }
    }
}

extern "C" void kernel_launch(void* const* d_in, const int* in_sizes, int n_in,
                              void* d_out, int out_size) {
    const float* features = (const float*)d_in[0];
    const float* gprob    = (const float*)d_in[1];
    const float* W        = (const float*)d_in[2];
    const float* bias     = (const float*)d_in[3];
    const int*   labels   = (const int*)d_in[4];
    float* out = (float*)d_out;

    static __nv_bfloat16* hA = nullptr;  // resolved device-symbol addresses
    static __nv_bfloat16 *lA, *hW, *lW;
    static bool init = false;
    if (!init) {
        cudaGetSymbolAddress((void**)&hA, g_Ahi);
        cudaGetSymbolAddress((void**)&lA, g_Alo);
        cudaGetSymbolAddress((void**)&hW, g_Whi);
        cudaGetSymbolAddress((void**)&lW, g_Wlo);
        cudaFuncSetAttribute(mhc_gemm, cudaFuncAttributeMaxDynamicSharedMemorySize, SMEM_GEMM);
        cudaFuncSetAttribute(mhc_scatter, cudaFuncAttributeMaxDynamicSharedMemorySize, SMEM_SCAT);
        init = true;
    }

    prep_kernel<<<1, 1024>>>(labels);
    prep_split<<<(B_ROWS * FDIM) / 1024, 256>>>(features, hA, lA);
    prep_split<<<(NCOLS * FDIM) / 1024, 256>>>(W, hW, lW);

    dim3 grid(NCOLS / BN, B_ROWS / BM);
    mhc_gemm<<<grid, 256, SMEM_GEMM>>>(gprob, bias);
    mhc_scatter<<<B_ROWS / 32, 256, SMEM_SCAT>>>(out);
}